// round 1
// baseline (speedup 1.0000x reference)
#include <cuda_runtime.h>
#include <math.h>
#include <stdint.h>

// ---------------- problem dims ----------------
#define NN_   2708   // n nodes
#define MF_   4096   // nfeat
#define MD_   2048   // dictionary atoms
#define NH_   1024   // hidden
#define NC_   64     // classes
#define PITER 100
#define FITER 20

// output layout (concatenated reference tuple, all f32)
#define OFF_LSM    0
#define CNT_LSM    (NN_*NC_)                    // 173312
#define OFF_XDEC   (OFF_LSM + CNT_LSM)          // 173312
#define CNT_XDEC   (NN_*MF_)                    // 11091968
#define OFF_GAMMA  (OFF_XDEC + CNT_XDEC)        // 11265280
#define CNT_GAMMA  (MD_*MF_)                    // 8388608
#define OFF_NORMS  (OFF_GAMMA + CNT_GAMMA)      // 19653888
#define TOTAL_OUT  (OFF_NORMS + FITER)          // 19653908

// ---------------- device scratch (static, no allocs) ----------------
__device__ float d_M  [(size_t)MD_*MD_];     // W^T W        16 MB
__device__ float d_G  [(size_t)MD_*MF_];     // Gamma        32 MB
__device__ float d_Z  [(size_t)MD_*MF_];     // Z            32 MB
__device__ float d_R  [(size_t)NN_*MF_];     // residual / x_dec fallback 44 MB
__device__ float d_XW1[(size_t)NN_*NH_];
__device__ float d_H  [(size_t)NN_*NH_];
__device__ float d_HW2[(size_t)NN_*NC_];
__device__ float d_O  [(size_t)NN_*NC_];
__device__ float d_xv [MD_];
__device__ float d_yv [MD_];
__device__ float d_acc[128];                 // [0..99] pm nm2, [100] ||Y||^2, [101..120] fista nm2
__device__ float d_sc [8];                   // [0]=c, [1]=eta, [3]=lam

// ---------------- init: zero accumulators, sniff lam from K ----------------
__global__ void init_kernel(const void* Kraw) {
    int t = threadIdx.x;
    if (t < 128) d_acc[t] = 0.f;
    if (t == 0) {
        uint32_t raw = *(const uint32_t*)Kraw;
        float f = __uint_as_float(raw);
        float lam;
        if (f >= 1e-30f && f <= 1e30f) lam = f;            // stored as float
        else                           lam = (float)(int)raw; // stored as int32
        d_sc[3] = lam;
    }
}

// ---------------- X0 = jax.random.normal(key(1), (1,2048)) via threefry2x32 ----------------
__device__ __forceinline__ uint32_t rotl32(uint32_t v, int r) { return (v << r) | (v >> (32 - r)); }

__device__ float erfinv_xla(float x) {  // XLA ErfInv32 (Giles polynomial)
    float w = -log1pf(-x * x);
    float p;
    if (w < 5.0f) {
        w -= 2.5f;
        p =               2.81022636e-08f;
        p = fmaf(p, w,    3.43273939e-07f);
        p = fmaf(p, w,   -3.5233877e-06f);
        p = fmaf(p, w,   -4.39150654e-06f);
        p = fmaf(p, w,    0.00021858087f);
        p = fmaf(p, w,   -0.00125372503f);
        p = fmaf(p, w,   -0.00417768164f);
        p = fmaf(p, w,    0.246640727f);
        p = fmaf(p, w,    1.50140941f);
    } else {
        w = sqrtf(w) - 3.0f;
        p =              -0.000200214257f;
        p = fmaf(p, w,    0.000100950558f);
        p = fmaf(p, w,    0.00134934322f);
        p = fmaf(p, w,   -0.00367342844f);
        p = fmaf(p, w,    0.00573950773f);
        p = fmaf(p, w,   -0.0076224613f);
        p = fmaf(p, w,    0.00943887047f);
        p = fmaf(p, w,    1.00167406f);
        p = fmaf(p, w,    2.83297682f);
    }
    return p * x;
}

__device__ __forceinline__ float bits_to_normal(uint32_t b) {
    uint32_t fb = (b >> 9) | 0x3f800000u;
    float f = __uint_as_float(fb) - 1.0f;          // [0,1)
    const float lo = -0.99999994f;                 // nextafter(-1,0)
    float u = fmaxf(lo, fmaf(f, 2.0f, lo));        // (hi-lo) rounds to 2.0f in f32
    return 1.41421356237309515f * erfinv_xla(u);
}

__global__ void init_x0_kernel() {
    int i = blockIdx.x * blockDim.x + threadIdx.x;
    if (i >= 1024) return;
    uint32_t x0 = (uint32_t)i, x1 = (uint32_t)(1024 + i);
    const uint32_t ks0 = 0u, ks1 = 1u, ks2 = 0x1BD11BDBu; // 0^1^0x1BD11BDA
    x0 += ks0; x1 += ks1;
    const int r0[4] = {13,15,26,6}, r1[4] = {17,29,16,24};
    #define TFROUND(r) { x0 += x1; x1 = rotl32(x1, r); x1 ^= x0; }
    // group 0 (r0), inject ks1, ks2+1
    TFROUND(r0[0]) TFROUND(r0[1]) TFROUND(r0[2]) TFROUND(r0[3]) x0 += ks1; x1 += ks2 + 1u;
    // group 1 (r1), inject ks2, ks0+2
    TFROUND(r1[0]) TFROUND(r1[1]) TFROUND(r1[2]) TFROUND(r1[3]) x0 += ks2; x1 += ks0 + 2u;
    // group 2 (r0), inject ks0, ks1+3
    TFROUND(r0[0]) TFROUND(r0[1]) TFROUND(r0[2]) TFROUND(r0[3]) x0 += ks0; x1 += ks1 + 3u;
    // group 3 (r1), inject ks1, ks2+4
    TFROUND(r1[0]) TFROUND(r1[1]) TFROUND(r1[2]) TFROUND(r1[3]) x0 += ks1; x1 += ks2 + 4u;
    // group 4 (r0), inject ks2, ks0+5
    TFROUND(r0[0]) TFROUND(r0[1]) TFROUND(r0[2]) TFROUND(r0[3]) x0 += ks2; x1 += ks0 + 5u;
    #undef TFROUND
    d_xv[i]        = bits_to_normal(x0);
    d_xv[1024 + i] = bits_to_normal(x1);
}

// ---------------- generic sum-of-squares reduction ----------------
__global__ void sumsq_kernel(const float* __restrict__ v, size_t n, float* acc) {
    float s = 0.f;
    for (size_t i = blockIdx.x * (size_t)blockDim.x + threadIdx.x; i < n;
         i += (size_t)gridDim.x * blockDim.x) {
        float t = v[i]; s += t * t;
    }
    for (int o = 16; o; o >>= 1) s += __shfl_down_sync(0xffffffffu, s, o);
    __shared__ float red[8];
    int lane = threadIdx.x & 31, w = threadIdx.x >> 5;
    if (lane == 0) red[w] = s;
    __syncthreads();
    if (threadIdx.x == 0) {
        float t = 0.f;
        int nw = blockDim.x >> 5;
        for (int i = 0; i < nw; i++) t += red[i];
        atomicAdd(acc, t);
    }
}

// ---------------- power method: y = M x, nm2 += ||y||^2 ----------------
__global__ void pm_matvec(const float* __restrict__ Mm, const float* __restrict__ x,
                          float* __restrict__ y, float* nm2) {
    __shared__ float xs[MD_];
    int tid = threadIdx.x;                        // 256
    for (int i = tid; i < MD_; i += 256) xs[i] = x[i];
    __syncthreads();
    int warp = tid >> 5, lane = tid & 31;
    int row = blockIdx.x * 8 + warp;
    const float* Mr = Mm + (size_t)row * MD_;
    float s = 0.f;
    #pragma unroll 4
    for (int i = lane; i < MD_; i += 32) s = fmaf(Mr[i], xs[i], s);
    for (int o = 16; o; o >>= 1) s += __shfl_down_sync(0xffffffffu, s, o);
    __shared__ float ws[8];
    if (lane == 0) { y[row] = s; ws[warp] = s * s; }
    __syncthreads();
    if (tid == 0) {
        float t = 0.f;
        for (int w = 0; w < 8; w++) t += ws[w];
        atomicAdd(nm2, t);
    }
}

__global__ void pm_scale(const float* __restrict__ y, float* __restrict__ x,
                         const float* nm2, int last) {
    int i = blockIdx.x * blockDim.x + threadIdx.x;
    float nm = sqrtf(*nm2);
    if (i < MD_) x[i] = y[i] / nm;
    if (last && i == 0) { d_sc[0] = nm; d_sc[1] = 1.0f / nm; }
}

// ---------------- main GEMM: 128x128x8 tile, 8x8/thread (split 4+4), fused epilogues ----------------
// TA=0: C[M,N] = A[M,K] * B[K,N].  TA=1: C[M,N] = A[K,M]^T * B[K,N].
// EPI: 0 store | 1 C=acc-aux, sumsq->nacc | 2 FISTA update | 3 Gamma0 | 4 relu(acc+bias) | 5 acc+bias
#define BM 128
#define BN 128
#define BK 8

template<int TA, int EPI>
__global__ void __launch_bounds__(256, 2) gemm_k(
    const float* __restrict__ A, const float* __restrict__ B, float* __restrict__ C,
    int M, int N, int K,
    const float* __restrict__ aux, float* out2, float mu, float* nacc)
{
    __shared__ float As[BK][BM + 4];
    __shared__ float Bs[BK][BN + 4];
    const int tid = threadIdx.x;
    const int row0 = blockIdx.y * BM, col0 = blockIdx.x * BN;
    const int tx = tid & 15, ty = tid >> 4;

    float acc[8][8];
    #pragma unroll
    for (int i = 0; i < 8; i++)
        #pragma unroll
        for (int j = 0; j < 8; j++) acc[i][j] = 0.f;

    const int nk = (K + BK - 1) / BK;
    for (int kt = 0; kt < nk; ++kt) {
        const int k0 = kt * BK;
        if (TA == 0) {
            const int ar = tid >> 1, ac = (tid & 1) << 2;
            const int gr = row0 + ar, gk = k0 + ac;
            float4 v = make_float4(0.f, 0.f, 0.f, 0.f);
            if (gr < M && gk < K) v = *(const float4*)(A + (size_t)gr * K + gk);
            As[ac + 0][ar] = v.x; As[ac + 1][ar] = v.y;
            As[ac + 2][ar] = v.z; As[ac + 3][ar] = v.w;
        } else {
            const int ak = tid >> 5, am = (tid & 31) << 2;
            const int gk = k0 + ak, gm = row0 + am;
            float4 v = make_float4(0.f, 0.f, 0.f, 0.f);
            if (gk < K && gm < M) v = *(const float4*)(A + (size_t)gk * M + gm);
            *(float4*)&As[ak][am] = v;
        }
        {
            const int bk = tid >> 5, bn = (tid & 31) << 2;
            const int gk = k0 + bk, gn = col0 + bn;
            float4 v = make_float4(0.f, 0.f, 0.f, 0.f);
            if (gk < K && gn < N) v = *(const float4*)(B + (size_t)gk * N + gn);
            *(float4*)&Bs[bk][bn] = v;
        }
        __syncthreads();
        #pragma unroll
        for (int kk = 0; kk < BK; ++kk) {
            float ar_[8], br_[8];
            *(float4*)&ar_[0] = *(const float4*)&As[kk][ty * 4];
            *(float4*)&ar_[4] = *(const float4*)&As[kk][ty * 4 + 64];
            *(float4*)&br_[0] = *(const float4*)&Bs[kk][tx * 4];
            *(float4*)&br_[4] = *(const float4*)&Bs[kk][tx * 4 + 64];
            #pragma unroll
            for (int i = 0; i < 8; i++)
                #pragma unroll
                for (int j = 0; j < 8; j++)
                    acc[i][j] = fmaf(ar_[i], br_[j], acc[i][j]);
        }
        __syncthreads();
    }

    // epilogue params
    float cval = 0.f, eta = 0.f, lam = 0.f, thr = 0.f;
    if (EPI == 2) { cval = d_sc[0]; eta = d_sc[1]; lam = d_sc[3]; thr = lam / cval; }
    if (EPI == 3) { eta = d_sc[1]; lam = d_sc[3]; }

    float vsum = 0.f;
    #pragma unroll
    for (int i = 0; i < 8; i++) {
        int r = row0 + ty * 4 + (i < 4 ? i : 60 + i);
        if (r >= M) continue;
        #pragma unroll
        for (int j = 0; j < 8; j++) {
            int c = col0 + tx * 4 + (j < 4 ? j : 60 + j);
            if (c >= N) continue;
            size_t idx = (size_t)r * N + c;
            float a = acc[i][j];
            if (EPI == 0) {
                C[idx] = a;
            } else if (EPI == 1) {
                float v = a - aux[idx]; C[idx] = v; vsum = fmaf(v, v, vsum);
            } else if (EPI == 2) {
                float zold = out2[idx];
                float gold = C[idx];
                float u = zold - eta * a;
                float g = copysignf(fmaxf(fabsf(u) - thr, 0.f), u);
                C[idx] = g;
                out2[idx] = g + mu * (g - gold);
            } else if (EPI == 3) {
                float u = eta * a;
                float g = copysignf(fmaxf(fabsf(u) - lam, 0.f), u);
                C[idx] = g; out2[idx] = g;
            } else if (EPI == 4) {
                C[idx] = fmaxf(a + aux[c], 0.f);
            } else if (EPI == 5) {
                C[idx] = a + aux[c];
            }
        }
    }
    if (EPI == 1) {
        for (int o = 16; o; o >>= 1) vsum += __shfl_down_sync(0xffffffffu, vsum, o);
        __shared__ float red[8];
        if ((tid & 31) == 0) red[tid >> 5] = vsum;
        __syncthreads();
        if (tid == 0) {
            float s = 0.f;
            for (int w = 0; w < 8; w++) s += red[w];
            atomicAdd(nacc, s);
        }
    }
}

// ---------------- small kernels ----------------
__global__ void copy4_kernel(const float4* __restrict__ src, float4* __restrict__ dst, size_t n4) {
    for (size_t i = blockIdx.x * (size_t)blockDim.x + threadIdx.x; i < n4;
         i += (size_t)gridDim.x * blockDim.x)
        dst[i] = src[i];
}

__global__ void lsm_kernel(const float* __restrict__ X, float* __restrict__ O, int nrows) {
    int row = blockIdx.x * 4 + (threadIdx.x >> 5);
    int lane = threadIdx.x & 31;
    if (row >= nrows) return;
    const float* xr = X + (size_t)row * NC_;
    float a = xr[lane], b = xr[lane + 32];
    float mx = fmaxf(a, b);
    for (int o = 16; o; o >>= 1) mx = fmaxf(mx, __shfl_xor_sync(0xffffffffu, mx, o));
    float se = expf(a - mx) + expf(b - mx);
    for (int o = 16; o; o >>= 1) se += __shfl_xor_sync(0xffffffffu, se, o);
    float l = logf(se);
    O[(size_t)row * NC_ + lane]      = a - mx - l;
    O[(size_t)row * NC_ + lane + 32] = b - mx - l;
}

__global__ void norms_kernel(float* outn) {
    int k = threadIdx.x;
    if (k < FITER) outn[k] = sqrtf(d_acc[101 + k]) / sqrtf(d_acc[100]);
}

// ---------------- host orchestration ----------------
static inline dim3 ggrid(int M, int N) { return dim3((N + BN - 1) / BN, (M + BM - 1) / BM); }

extern "C" void kernel_launch(void* const* d_in, const int* in_sizes, int n_in,
                              void* d_out, int out_size) {
    const float* x   = (const float*)d_in[0];
    const float* adj = (const float*)d_in[1];
    const float* g1w = (const float*)d_in[2];
    const float* g1b = (const float*)d_in[3];
    const float* g2w = (const float*)d_in[4];
    const float* g2b = (const float*)d_in[5];
    const float* Wd  = (const float*)d_in[6];
    const void*  Kp  = d_in[7];
    float* out = (float*)d_out;
    bool full = out_size >= TOTAL_OUT;

    float *pM, *pG, *pZ, *pR, *pXW1, *pH, *pHW2, *pO, *pxv, *pyv, *pacc;
    cudaGetSymbolAddress((void**)&pM, d_M);
    cudaGetSymbolAddress((void**)&pG, d_G);
    cudaGetSymbolAddress((void**)&pZ, d_Z);
    cudaGetSymbolAddress((void**)&pR, d_R);
    cudaGetSymbolAddress((void**)&pXW1, d_XW1);
    cudaGetSymbolAddress((void**)&pH, d_H);
    cudaGetSymbolAddress((void**)&pHW2, d_HW2);
    cudaGetSymbolAddress((void**)&pO, d_O);
    cudaGetSymbolAddress((void**)&pxv, d_xv);
    cudaGetSymbolAddress((void**)&pyv, d_yv);
    cudaGetSymbolAddress((void**)&pacc, d_acc);

    // FISTA momentum schedule (f32, matching reference)
    float mus[FITER];
    {
        float t = 1.0f;
        for (int k = 0; k < FITER; k++) {
            float tn = (1.0f + sqrtf(1.0f + 4.0f * t * t)) * 0.5f;
            mus[k] = (t - 1.0f) / tn;
            t = tn;
        }
    }

    // 1. init accumulators + lam
    init_kernel<<<1, 128>>>(Kp);
    // 2. X0 from threefry
    init_x0_kernel<<<4, 256>>>();
    // 3. ||Y||^2
    sumsq_kernel<<<1024, 256>>>(x, (size_t)NN_ * MF_, pacc + 100);
    // 4. M = W^T W   (TN: M=2048,N=2048,K=2708)
    gemm_k<1, 0><<<ggrid(MD_, MD_), 256>>>(Wd, Wd, pM, MD_, MD_, NN_, nullptr, nullptr, 0.f, nullptr);
    // 5. power iterations
    for (int it = 0; it < PITER; it++) {
        pm_matvec<<<MD_ / 8, 256>>>(pM, pxv, pyv, pacc + it);
        pm_scale<<<MD_ / 256, 256>>>(pyv, pxv, pacc + it, it == PITER - 1);
    }
    // 6. Gamma0 = soft(eta * W^T Y, lam); Z = Gamma0
    gemm_k<1, 3><<<ggrid(MD_, MF_), 256>>>(Wd, x, pG, MD_, MF_, NN_, nullptr, pZ, 0.f, nullptr);
    // 7. FISTA
    for (int k = 0; k < FITER; k++) {
        // R = W Z - Y, accumulate ||R||^2
        gemm_k<0, 1><<<ggrid(NN_, MF_), 256>>>(Wd, pZ, pR, NN_, MF_, MD_, x, nullptr, 0.f, pacc + 101 + k);
        // T = W^T R; G = soft(Z - eta T, lam/c); Z = G + mu (G - Gold)
        gemm_k<1, 2><<<ggrid(MD_, MF_), 256>>>(Wd, pR, pG, MD_, MF_, NN_, nullptr, pZ, mus[k], nullptr);
    }
    // 8. x_dec = W Gamma -> straight into output region (or scratch if out too small)
    float* xdec = full ? (out + OFF_XDEC) : pR;
    gemm_k<0, 0><<<ggrid(NN_, MF_), 256>>>(Wd, pG, xdec, NN_, MF_, MD_, nullptr, nullptr, 0.f, nullptr);
    // 9. Gamma copy to output
    if (full)
        copy4_kernel<<<1024, 256>>>((const float4*)pG, (float4*)(out + OFF_GAMMA), (size_t)CNT_GAMMA / 4);
    // 10. XW1 = x_dec @ gc1_w
    gemm_k<0, 0><<<ggrid(NN_, NH_), 256>>>(xdec, g1w, pXW1, NN_, NH_, MF_, nullptr, nullptr, 0.f, nullptr);
    // 11. H = relu(adj @ XW1 + b1)
    gemm_k<0, 4><<<ggrid(NN_, NH_), 256>>>(adj, pXW1, pH, NN_, NH_, NN_, g1b, nullptr, 0.f, nullptr);
    // 12. HW2 = H @ gc2_w
    gemm_k<0, 0><<<ggrid(NN_, NC_), 256>>>(pH, g2w, pHW2, NN_, NC_, NH_, nullptr, nullptr, 0.f, nullptr);
    // 13. O = adj @ HW2 + b2
    gemm_k<0, 5><<<ggrid(NN_, NC_), 256>>>(adj, pHW2, pO, NN_, NC_, NN_, g2b, nullptr, 0.f, nullptr);
    // 14. log_softmax -> out[0:173312]
    lsm_kernel<<<(NN_ + 3) / 4, 128>>>(pO, out + OFF_LSM, NN_);
    // 15. norms
    if (full) norms_kernel<<<1, 32>>>(out + OFF_NORMS);
}